// round 15
// baseline (speedup 1.0000x reference)
#include <cuda_runtime.h>
#include <math.h>

#define PI_F 3.14159265358979323846f

// ---------------- device globals ----------------
__device__ float2 g_Xf[16 * 256 * 256];
__device__ float2 g_A [128 * 256 * 256];
__device__ float2 g_B [128 * 256 * 256];
__device__ float  g_S [16 * 417 * 256];
__device__ float  g_psi[2392064];
__device__ float  g_phi[87040];
__device__ float2 g_tw[128];
__device__ float  g_part[128 * 1024 * 16];
__device__ float  g_h1[16 * 1024];
__device__ float  g_h2[16 * 512];
__device__ float  g_h3[16 * 128];

__device__ __forceinline__ float2 cmul(float2 a, float2 b)
{
    return make_float2(a.x * b.x - a.y * b.y, a.x * b.y + a.y * b.x);
}

// vectorized fold: R contiguous complex terms * R contiguous filter floats
template<int R>
__device__ __forceinline__ void fold_term(const float2* __restrict__ Ir,
                                          const float* __restrict__ Fr,
                                          float& sx, float& sy)
{
    if (R == 2) {
        float4 z = *(const float4*)Ir;
        float2 f = *(const float2*)Fr;
        sx += z.x * f.x + z.z * f.y;
        sy += z.y * f.x + z.w * f.y;
    } else {
        #pragma unroll
        for (int s = 0; s < R / 4; s++) {
            float4 a = ((const float4*)Ir)[2 * s];
            float4 b = ((const float4*)Ir)[2 * s + 1];
            float4 f = ((const float4*)Fr)[s];
            sx += a.x * f.x + a.z * f.y + b.x * f.z + b.z * f.w;
            sy += a.y * f.x + a.w * f.y + b.y * f.z + b.w * f.w;
        }
    }
}

// ---------------- DIF (fwd) / DIT (inv), radix-2^2, no bit-reversal ----------------
template<int N, int LOGN, int NFFT, int LOGNF, int NTH, bool CMAJ>
__device__ __forceinline__ void fft_inv(float2* sh, int stride, int fstride,
                                        const float2* tw, int tid)
{
    constexpr int HTOT = NFFT * (N >> 1);
    constexpr int TOT4 = NFFT * (N >> 2);
    int s = 1;
    if (LOGN & 1) {
        for (int q = 0; q < (HTOT + NTH - 1) / NTH; q++) {
            int w = tid + q * NTH;
            if ((HTOT % NTH) && w >= HTOT) break;
            int f, r;
            if (CMAJ) { f = w & (NFFT - 1); r = w >> LOGNF; }
            else      { f = w >> (LOGN - 1); r = w & ((N >> 1) - 1); }
            float2* p = sh + f * fstride;
            int i0 = (2 * r) * stride;
            float2 a = p[i0], b = p[i0 + stride];
            p[i0]          = make_float2(a.x + b.x, a.y + b.y);
            p[i0 + stride] = make_float2(a.x - b.x, a.y - b.y);
        }
        __syncthreads();
        s = 2;
    }
    for (; s < LOGN; s += 2) {
        for (int q = 0; q < (TOT4 + NTH - 1) / NTH; q++) {
            int w = tid + q * NTH;
            if ((TOT4 % NTH) && w >= TOT4) break;
            int f, r;
            if (CMAJ) { f = w & (NFFT - 1); r = w >> LOGNF; }
            else      { f = w >> (LOGN - 2); r = w & ((N >> 2) - 1); }
            int h = 1 << (s - 1);
            int j = r & (h - 1);
            int base = (r >> (s - 1)) << (s + 1);
            float2 W1 = tw[j << (LOGN - s)];
            float2 W2 = tw[j << (LOGN - s - 1)];
            float2* p = sh + f * fstride;
            int hs = h * stride;
            int i0 = (base + j) * stride;
            float2 x0 = p[i0], x1 = p[i0 + hs], x2 = p[i0 + 2 * hs], x3 = p[i0 + 3 * hs];
            float2 t1 = cmul(W1, x1), t3 = cmul(W1, x3);
            float2 y0 = make_float2(x0.x + t1.x, x0.y + t1.y);
            float2 y1 = make_float2(x0.x - t1.x, x0.y - t1.y);
            float2 y2 = make_float2(x2.x + t3.x, x2.y + t3.y);
            float2 y3 = make_float2(x2.x - t3.x, x2.y - t3.y);
            float2 u = cmul(W2, y2);
            float2 iW2 = make_float2(-W2.y, W2.x);
            float2 v = cmul(iW2, y3);
            p[i0]          = make_float2(y0.x + u.x, y0.y + u.y);
            p[i0 + 2 * hs] = make_float2(y0.x - u.x, y0.y - u.y);
            p[i0 + hs]     = make_float2(y1.x + v.x, y1.y + v.y);
            p[i0 + 3 * hs] = make_float2(y1.x - v.x, y1.y - v.y);
        }
        __syncthreads();
    }
}

template<int N, int LOGN, int NFFT, int LOGNF, int NTH, bool CMAJ>
__device__ __forceinline__ void fft_fwd(float2* sh, int stride, int fstride,
                                        const float2* tw, int tid)
{
    constexpr int HTOT = NFFT * (N >> 1);
    constexpr int TOT4 = NFFT * (N >> 2);
    constexpr int SLO = (LOGN & 1) ? 3 : 2;
    for (int s = LOGN; s >= SLO; s -= 2) {
        for (int q = 0; q < (TOT4 + NTH - 1) / NTH; q++) {
            int w = tid + q * NTH;
            if ((TOT4 % NTH) && w >= TOT4) break;
            int f, r;
            if (CMAJ) { f = w & (NFFT - 1); r = w >> LOGNF; }
            else      { f = w >> (LOGN - 2); r = w & ((N >> 2) - 1); }
            int h = 1 << (s - 2);
            int j = r & (h - 1);
            int base = (r >> (s - 2)) << s;
            float2 W2 = tw[j << (LOGN - s)];
            float2 W1 = tw[j << (LOGN - s + 1)];
            float2 W2c = make_float2(W2.x, -W2.y);
            float2 W1c = make_float2(W1.x, -W1.y);
            float2 miW2c = make_float2(-W2.y, -W2.x);
            float2* p = sh + f * fstride;
            int hs = h * stride;
            int i0 = (base + j) * stride;
            float2 x0 = p[i0], x1 = p[i0 + hs], x2 = p[i0 + 2 * hs], x3 = p[i0 + 3 * hs];
            float2 p0 = make_float2(x0.x + x2.x, x0.y + x2.y);
            float2 q2 = make_float2(x0.x - x2.x, x0.y - x2.y);
            float2 p1 = make_float2(x1.x + x3.x, x1.y + x3.y);
            float2 q3 = make_float2(x1.x - x3.x, x1.y - x3.y);
            float2 t2 = cmul(W2c, q2);
            float2 t3 = cmul(miW2c, q3);
            float2 d01 = make_float2(p0.x - p1.x, p0.y - p1.y);
            float2 d23 = make_float2(t2.x - t3.x, t2.y - t3.y);
            p[i0]          = make_float2(p0.x + p1.x, p0.y + p1.y);
            p[i0 + hs]     = cmul(W1c, d01);
            p[i0 + 2 * hs] = make_float2(t2.x + t3.x, t2.y + t3.y);
            p[i0 + 3 * hs] = cmul(W1c, d23);
        }
        __syncthreads();
    }
    if (LOGN & 1) {
        for (int q = 0; q < (HTOT + NTH - 1) / NTH; q++) {
            int w = tid + q * NTH;
            if ((HTOT % NTH) && w >= HTOT) break;
            int f, r;
            if (CMAJ) { f = w & (NFFT - 1); r = w >> LOGNF; }
            else      { f = w >> (LOGN - 1); r = w & ((N >> 1) - 1); }
            float2* p = sh + f * fstride;
            int i0 = (2 * r) * stride;
            float2 a = p[i0], b = p[i0 + stride];
            p[i0]          = make_float2(a.x + b.x, a.y + b.y);
            p[i0 + stride] = make_float2(a.x - b.x, a.y - b.y);
        }
        __syncthreads();
    }
}

// ---------------- multi-tile variants: TILES square NxN tiles, stride TSTR ----------------
template<int N, int LOGN, int TILES, int TSTR, int NTH, bool CMAJ>
__device__ __forceinline__ void fft_inv_mt(float2* shb, int stride, int fstride,
                                           const float2* tw, int tid)
{
    constexpr int PT2 = N * (N >> 1);
    constexpr int PT4 = N * (N >> 2);
    constexpr int TOT2 = TILES * PT2;
    constexpr int TOT4 = TILES * PT4;
    int s = 1;
    if (LOGN & 1) {
        for (int q = 0; q < (TOT2 + NTH - 1) / NTH; q++) {
            int w = tid + q * NTH;
            if ((TOT2 % NTH) && w >= TOT2) break;
            int t = w >> (2 * LOGN - 1);
            int rem = w & (PT2 - 1);
            int f, r;
            if (CMAJ) { f = rem & (N - 1); r = rem >> LOGN; }
            else      { f = rem >> (LOGN - 1); r = rem & ((N >> 1) - 1); }
            float2* p = shb + t * TSTR + f * fstride;
            int i0 = (2 * r) * stride;
            float2 a = p[i0], b = p[i0 + stride];
            p[i0]          = make_float2(a.x + b.x, a.y + b.y);
            p[i0 + stride] = make_float2(a.x - b.x, a.y - b.y);
        }
        __syncthreads();
        s = 2;
    }
    for (; s < LOGN; s += 2) {
        for (int q = 0; q < (TOT4 + NTH - 1) / NTH; q++) {
            int w = tid + q * NTH;
            if ((TOT4 % NTH) && w >= TOT4) break;
            int t = w >> (2 * LOGN - 2);
            int rem = w & (PT4 - 1);
            int f, r;
            if (CMAJ) { f = rem & (N - 1); r = rem >> LOGN; }
            else      { f = rem >> (LOGN - 2); r = rem & ((N >> 2) - 1); }
            int h = 1 << (s - 1);
            int j = r & (h - 1);
            int base = (r >> (s - 1)) << (s + 1);
            float2 W1 = tw[j << (LOGN - s)];
            float2 W2 = tw[j << (LOGN - s - 1)];
            float2* p = shb + t * TSTR + f * fstride;
            int hs = h * stride;
            int i0 = (base + j) * stride;
            float2 x0 = p[i0], x1 = p[i0 + hs], x2 = p[i0 + 2 * hs], x3 = p[i0 + 3 * hs];
            float2 t1 = cmul(W1, x1), t3 = cmul(W1, x3);
            float2 y0 = make_float2(x0.x + t1.x, x0.y + t1.y);
            float2 y1 = make_float2(x0.x - t1.x, x0.y - t1.y);
            float2 y2 = make_float2(x2.x + t3.x, x2.y + t3.y);
            float2 y3 = make_float2(x2.x - t3.x, x2.y - t3.y);
            float2 u = cmul(W2, y2);
            float2 iW2 = make_float2(-W2.y, W2.x);
            float2 v = cmul(iW2, y3);
            p[i0]          = make_float2(y0.x + u.x, y0.y + u.y);
            p[i0 + 2 * hs] = make_float2(y0.x - u.x, y0.y - u.y);
            p[i0 + hs]     = make_float2(y1.x + v.x, y1.y + v.y);
            p[i0 + 3 * hs] = make_float2(y1.x - v.x, y1.y - v.y);
        }
        __syncthreads();
    }
}

template<int N, int LOGN, int TILES, int TSTR, int NTH, bool CMAJ>
__device__ __forceinline__ void fft_fwd_mt(float2* shb, int stride, int fstride,
                                           const float2* tw, int tid)
{
    constexpr int PT2 = N * (N >> 1);
    constexpr int PT4 = N * (N >> 2);
    constexpr int TOT2 = TILES * PT2;
    constexpr int TOT4 = TILES * PT4;
    constexpr int SLO = (LOGN & 1) ? 3 : 2;
    for (int s = LOGN; s >= SLO; s -= 2) {
        for (int q = 0; q < (TOT4 + NTH - 1) / NTH; q++) {
            int w = tid + q * NTH;
            if ((TOT4 % NTH) && w >= TOT4) break;
            int t = w >> (2 * LOGN - 2);
            int rem = w & (PT4 - 1);
            int f, r;
            if (CMAJ) { f = rem & (N - 1); r = rem >> LOGN; }
            else      { f = rem >> (LOGN - 2); r = rem & ((N >> 2) - 1); }
            int h = 1 << (s - 2);
            int j = r & (h - 1);
            int base = (r >> (s - 2)) << s;
            float2 W2 = tw[j << (LOGN - s)];
            float2 W1 = tw[j << (LOGN - s + 1)];
            float2 W2c = make_float2(W2.x, -W2.y);
            float2 W1c = make_float2(W1.x, -W1.y);
            float2 miW2c = make_float2(-W2.y, -W2.x);
            float2* p = shb + t * TSTR + f * fstride;
            int hs = h * stride;
            int i0 = (base + j) * stride;
            float2 x0 = p[i0], x1 = p[i0 + hs], x2 = p[i0 + 2 * hs], x3 = p[i0 + 3 * hs];
            float2 p0 = make_float2(x0.x + x2.x, x0.y + x2.y);
            float2 q2 = make_float2(x0.x - x2.x, x0.y - x2.y);
            float2 p1 = make_float2(x1.x + x3.x, x1.y + x3.y);
            float2 q3 = make_float2(x1.x - x3.x, x1.y - x3.y);
            float2 t2 = cmul(W2c, q2);
            float2 t3 = cmul(miW2c, q3);
            float2 d01 = make_float2(p0.x - p1.x, p0.y - p1.y);
            float2 d23 = make_float2(t2.x - t3.x, t2.y - t3.y);
            p[i0]          = make_float2(p0.x + p1.x, p0.y + p1.y);
            p[i0 + hs]     = cmul(W1c, d01);
            p[i0 + 2 * hs] = make_float2(t2.x + t3.x, t2.y + t3.y);
            p[i0 + 3 * hs] = cmul(W1c, d23);
        }
        __syncthreads();
    }
    if (LOGN & 1) {
        for (int q = 0; q < (TOT2 + NTH - 1) / NTH; q++) {
            int w = tid + q * NTH;
            if ((TOT2 % NTH) && w >= TOT2) break;
            int t = w >> (2 * LOGN - 1);
            int rem = w & (PT2 - 1);
            int f, r;
            if (CMAJ) { f = rem & (N - 1); r = rem >> LOGN; }
            else      { f = rem >> (LOGN - 1); r = rem & ((N >> 1) - 1); }
            float2* p = shb + t * TSTR + f * fstride;
            int i0 = (2 * r) * stride;
            float2 a = p[i0], b = p[i0 + stride];
            p[i0]          = make_float2(a.x + b.x, a.y + b.y);
            p[i0 + stride] = make_float2(a.x - b.x, a.y - b.y);
        }
        __syncthreads();
    }
}

template<int N, int NTH>
__device__ __forceinline__ void load_tw(float2* tws, const float2* gtw, int tid)
{
    for (int k = tid; k < N / 2; k += NTH) tws[k] = gtw[k * (256 / N)];
}

// ---------------- filter / table generation (bit-reversed frequency layout) ----------------
__global__ void kgen_tw(float2* tw)
{
    int k = threadIdx.x;
    if (k < 128) {
        float s, c;
        __sincosf(2.0f * PI_F * (float)k / 256.0f, &s, &c);
        tw[k] = make_float2(c, s);
    }
}

__global__ void kgen_psi(float* __restrict__ psi)
{
    int fi = blockIdx.x;
    int bank = fi >> 3;
    int l = fi & 7;
    int m, js, logm;
    long off;
    if (bank < 4)      { m = 256; js = bank; off = (long)bank * 8 * 65536; logm = 8; }
    else if (bank == 4){ m = 128; js = 1;    off = 4L * 8 * 65536;               logm = 7; }
    else if (bank == 5){ m = 128; js = 2;    off = 4L * 8 * 65536 + 8L * 16384;  logm = 7; }
    else               { m = 64;  js = 1;    off = 4L * 8 * 65536 + 16L * 16384; logm = 6; }
    float* F = psi + off + (long)l * m * m;
    float sigma = 0.8f * (float)(1 << js);
    float xi = (3.0f * PI_F / 4.0f) / (float)(1 << js);
    float th = (float)l * PI_F / 8.0f;
    float st, ct;
    __sincosf(th, &st, &ct);
    float s2 = 0.5f * sigma * sigma;
    float beta = expf(-s2 * xi * xi);
    float mx = 0.0f;
    int tid = threadIdx.x;
    int half = m >> 1;
    for (int idx = tid; idx < m * m; idx += 256) {
        int pu = idx / m, pv = idx - (idx / m) * m;
        int u = (int)(__brev((unsigned)pu) >> (32 - logm));
        int v = (int)(__brev((unsigned)pv) >> (32 - logm));
        float kx = 2.0f * PI_F * ((u < half) ? (float)u : (float)(u - m)) / (float)m;
        float ky = 2.0f * PI_F * ((v < half) ? (float)v : (float)(v - m)) / (float)m;
        float w1 =  kx * ct + ky * st;
        float w2 = -kx * st + ky * ct;
        float sw2 = 0.5f * w2;
        float a   = expf(-s2 * ((w1 - xi) * (w1 - xi) + sw2 * sw2));
        float env = expf(-s2 * (w1 * w1 + sw2 * sw2));
        float fv = a - beta * env;
        F[idx] = fv;
        mx = fmaxf(mx, fv);
    }
    __shared__ float red[256];
    red[tid] = mx;
    __syncthreads();
    for (int s = 128; s > 0; s >>= 1) {
        if (tid < s) red[tid] = fmaxf(red[tid], red[tid + s]);
        __syncthreads();
    }
    float inv = 1.0f / fmaxf(red[0], 1e-12f);
    for (int idx = tid; idx < m * m; idx += 256) F[idx] *= inv;
}

__global__ void kgen_phi(float* __restrict__ phi)
{
    int r = blockIdx.x;
    int m = 256 >> r;
    int logm = 8 - r;
    long off = (r == 0) ? 0 : (r == 1) ? 65536 : (r == 2) ? 81920 : 86016;
    float sigma = 0.8f * (float)(1 << (4 - r));
    float s2 = 0.5f * sigma * sigma;
    float* F = phi + off;
    int half = m >> 1;
    for (int idx = threadIdx.x; idx < m * m; idx += 256) {
        int pu = idx / m, pv = idx - (idx / m) * m;
        int u = (int)(__brev((unsigned)pu) >> (32 - logm));
        int v = (int)(__brev((unsigned)pv) >> (32 - logm));
        float kx = 2.0f * PI_F * ((u < half) ? (float)u : (float)(u - m)) / (float)m;
        float ky = 2.0f * PI_F * ((v < half) ? (float)v : (float)(v - m)) / (float)m;
        F[idx] = expf(-s2 * (kx * kx + ky * ky));
    }
}

// ---------------- 256-size (j1=0) path ----------------
__global__ void __launch_bounds__(256) kfwd_rows_real(
    const float* __restrict__ x, float2* __restrict__ Xf, const float2* __restrict__ gtw)
{
    __shared__ float2 sh[1024];
    __shared__ float2 tws[128];
    int tid = threadIdx.x;
    load_tw<256, 256>(tws, gtw, tid);
    const float4* X4 = (const float4*)(x + (long)blockIdx.x * 1024);
    {
        float4 v = X4[tid];
        sh[4 * tid + 0] = make_float2(v.x, 0.0f);
        sh[4 * tid + 1] = make_float2(v.y, 0.0f);
        sh[4 * tid + 2] = make_float2(v.z, 0.0f);
        sh[4 * tid + 3] = make_float2(v.w, 0.0f);
    }
    __syncthreads();
    fft_fwd<256, 8, 4, 2, 256, false>(sh, 1, 256, tws, tid);
    float4* O4 = (float4*)(Xf + (long)blockIdx.x * 1024);
    const float4* S4 = (const float4*)sh;
    O4[tid] = S4[tid];
    O4[tid + 256] = S4[tid + 256];
}

__global__ void __launch_bounds__(256) kfwd_cols256(
    float2* __restrict__ d, const float2* __restrict__ gtw)
{
    extern __shared__ float2 dsh[];
    float2* sh = dsh;
    float2* tws = dsh + 256 * 17;
    int tid = threadIdx.x;
    load_tw<256, 256>(tws, gtw, tid);
    int img = blockIdx.x >> 4, c0 = (blockIdx.x & 15) << 4;
    float2* D = d + (long)img * 65536 + c0;
    for (int idx = tid; idx < 2048; idx += 256) {
        int i = idx >> 3, c = (idx & 7) * 2;
        float4 v = *(const float4*)(D + (long)i * 256 + c);
        sh[i * 17 + c]     = make_float2(v.x, v.y);
        sh[i * 17 + c + 1] = make_float2(v.z, v.w);
    }
    __syncthreads();
    fft_fwd<256, 8, 16, 4, 256, true>(sh, 17, 1, tws, tid);
    for (int idx = tid; idx < 2048; idx += 256) {
        int i = idx >> 3, c = (idx & 7) * 2;
        float2 a = sh[i * 17 + c], b = sh[i * 17 + c + 1];
        *(float4*)(D + (long)i * 256 + c) = make_float4(a.x, a.y, b.x, b.y);
    }
}

__global__ void __launch_bounds__(256) kfilt_rows(
    const float2* __restrict__ Xf, const float* __restrict__ psi,
    float2* __restrict__ A, const float2* __restrict__ gtw)
{
    __shared__ float2 sh[1024];
    __shared__ float2 tws[128];
    int tid = threadIdx.x;
    load_tw<256, 256>(tws, gtw, tid);
    int o = blockIdx.x >> 6, rg = blockIdx.x & 63;
    int img = o >> 3, l = o & 7;
    const float4* I4 = (const float4*)(Xf + (long)img * 65536 + rg * 1024);
    const float2* F2 = (const float2*)(psi + (long)l * 65536 + rg * 1024);
    const float sc = 1.0f / 256.0f;
    for (int i = tid; i < 512; i += 256) {
        float4 z = I4[i];
        float2 f = F2[i];
        sh[2 * i]     = make_float2(z.x * f.x * sc, z.y * f.x * sc);
        sh[2 * i + 1] = make_float2(z.z * f.y * sc, z.w * f.y * sc);
    }
    __syncthreads();
    fft_inv<256, 8, 4, 2, 256, false>(sh, 1, 256, tws, tid);
    float4* O4 = (float4*)(A + (long)o * 65536 + rg * 1024);
    const float4* S4 = (const float4*)sh;
    O4[tid] = S4[tid];
    O4[tid + 256] = S4[tid + 256];
}

__global__ void __launch_bounds__(256) kcols_mod256(
    const float2* __restrict__ in, float2* __restrict__ out, const float2* __restrict__ gtw)
{
    extern __shared__ float2 dsh[];
    float2* sh = dsh;
    float2* tws = dsh + 256 * 17;
    int tid = threadIdx.x;
    load_tw<256, 256>(tws, gtw, tid);
    int img = blockIdx.x >> 4, c0 = (blockIdx.x & 15) << 4;
    const float2* I = in  + (long)img * 65536 + c0;
    float2*       O = out + (long)img * 65536 + c0;
    for (int idx = tid; idx < 2048; idx += 256) {
        int i = idx >> 3, c = (idx & 7) * 2;
        float4 v = *(const float4*)(I + (long)i * 256 + c);
        sh[i * 17 + c]     = make_float2(v.x, v.y);
        sh[i * 17 + c + 1] = make_float2(v.z, v.w);
    }
    __syncthreads();
    fft_inv<256, 8, 16, 4, 256, true>(sh, 17, 1, tws, tid);
    const float inv = 1.0f / 256.0f;
    for (int idx = tid; idx < 4096; idx += 256) {
        int i = idx >> 4, c = idx & 15;
        float2 z = sh[i * 17 + c];
        sh[i * 17 + c] = make_float2(sqrtf(z.x * z.x + z.y * z.y) * inv, 0.0f);
    }
    __syncthreads();
    fft_fwd<256, 8, 16, 4, 256, true>(sh, 17, 1, tws, tid);
    for (int idx = tid; idx < 2048; idx += 256) {
        int i = idx >> 3, c = (idx & 7) * 2;
        float2 a = sh[i * 17 + c], b = sh[i * 17 + c + 1];
        *(float4*)(O + (long)i * 256 + c) = make_float4(a.x, a.y, b.x, b.y);
    }
}

__global__ void __launch_bounds__(256) kfwd_rows(
    float2* __restrict__ d, const float2* __restrict__ gtw)
{
    __shared__ float2 sh[1024];
    __shared__ float2 tws[128];
    int tid = threadIdx.x;
    load_tw<256, 256>(tws, gtw, tid);
    float4* D4 = (float4*)(d + (long)blockIdx.x * 1024);
    float4* S4 = (float4*)sh;
    S4[tid] = D4[tid];
    S4[tid + 256] = D4[tid + 256];
    __syncthreads();
    fft_fwd<256, 8, 4, 2, 256, false>(sh, 1, 256, tws, tid);
    D4[tid] = S4[tid];
    D4[tid + 256] = S4[tid + 256];
}

// phi fold (256 -> 16) + 16x16 inverse FFT -> S
__global__ void __launch_bounds__(256) kphi16(
    const float2* __restrict__ in, const float* __restrict__ phi,
    float* __restrict__ S, const float2* __restrict__ gtw, int chBase, int CH)
{
    __shared__ float2 t16[16 * 17];
    __shared__ float2 tw16[8];
    int tid = threadIdx.x;
    if (tid < 8) tw16[tid] = gtw[tid * 16];
    int o = blockIdx.x;
    const float2* I = in + (long)o * 65536;
    const float ps = 1.0f / 65536.0f;
    int u = tid >> 4, v = tid & 15;
    float sx = 0.0f, sy = 0.0f;
    #pragma unroll 4
    for (int s1 = 0; s1 < 16; s1++) {
        const float2* Ir = I + (u * 16 + s1) * 256 + v * 16;
        const float*  Fr = phi + (u * 16 + s1) * 256 + v * 16;
        fold_term<16>(Ir, Fr, sx, sy);
    }
    t16[u * 17 + v] = make_float2(sx * ps, sy * ps);
    __syncthreads();
    fft_inv<16, 4, 16, 4, 256, false>(t16, 1, 17, tw16, tid);
    fft_inv<16, 4, 16, 4, 256, true >(t16, 17, 1, tw16, tid);
    int b = o / CH;
    int c = chBase + (o - b * CH);
    float* Out = S + ((long)b * 417 + c) * 256;
    Out[tid] = t16[u * 17 + v].x;
}

// ---------------- fused first-order small kernels ----------------
template<int N, int LOGN, int NTH>
__global__ void __launch_bounds__(NTH) k_first_small(
    const float2* __restrict__ Xf, const float* __restrict__ psi,
    const float* __restrict__ phi, float2* __restrict__ Bout,
    float* __restrict__ S, const float2* __restrict__ gtw, int chBase)
{
    extern __shared__ float2 dsh[];
    constexpr int P = N + 1;
    float2* sh   = dsh;
    float2* tws  = sh + N * P;
    float2* tw16 = tws + N / 2;
    float2* t16  = tw16 + 8;
    int tid = threadIdx.x;
    load_tw<N, NTH>(tws, gtw, tid);
    for (int k = tid; k < 8; k += NTH) tw16[k] = gtw[k * 16];
    int o = blockIdx.x;
    int img = o >> 3, l = o & 7;
    const float2* I = Xf + (long)img * 65536;
    const float*  F = psi + (long)l * 65536;
    constexpr int R = 256 / N;
    const float fs = 1.0f / 65536.0f;
    for (int idx = tid; idx < N * N; idx += NTH) {
        int u = idx >> LOGN, v = idx & (N - 1);
        float sx = 0.0f, sy = 0.0f;
        #pragma unroll
        for (int s1 = 0; s1 < R; s1++) {
            fold_term<R>(I + (long)(u * R + s1) * 256 + v * R,
                         F + (long)(u * R + s1) * 256 + v * R, sx, sy);
        }
        sh[u * P + v] = make_float2(sx * fs, sy * fs);
    }
    __syncthreads();
    fft_inv<N, LOGN, N, LOGN, NTH, false>(sh, 1, P, tws, tid);
    fft_inv<N, LOGN, N, LOGN, NTH, true >(sh, P, 1, tws, tid);
    for (int idx = tid; idx < N * N; idx += NTH) {
        int u = idx >> LOGN, v = idx & (N - 1);
        float2 z = sh[u * P + v];
        sh[u * P + v] = make_float2(sqrtf(z.x * z.x + z.y * z.y), 0.0f);
    }
    __syncthreads();
    fft_fwd<N, LOGN, N, LOGN, NTH, false>(sh, 1, P, tws, tid);
    fft_fwd<N, LOGN, N, LOGN, NTH, true >(sh, P, 1, tws, tid);
    float2* O = Bout + (long)o * N * N;
    for (int idx = tid; idx < N * N; idx += NTH) {
        int u = idx >> LOGN, v = idx & (N - 1);
        O[idx] = sh[u * P + v];
    }
    const float ps = 1.0f / ((float)N * (float)N);
    constexpr int R2 = N / 16;
    for (int idx = tid; idx < 256; idx += NTH) {
        int u = idx >> 4, v = idx & 15;
        float sx = 0.0f, sy = 0.0f;
        for (int s1 = 0; s1 < R2; s1++) {
            int U = u * R2 + s1;
            #pragma unroll 4
            for (int s2 = 0; s2 < R2; s2++) {
                int V = v * R2 + s2;
                float f = phi[U * N + V];
                float2 z = sh[U * P + V];
                sx += z.x * f;
                sy += z.y * f;
            }
        }
        t16[u * 17 + v] = make_float2(sx * ps, sy * ps);
    }
    __syncthreads();
    fft_inv<16, 4, 16, 4, NTH, false>(t16, 1, 17, tw16, tid);
    fft_inv<16, 4, 16, 4, NTH, true >(t16, 17, 1, tw16, tid);
    float* Out = S + ((long)img * 417 + chBase + l) * 256;
    for (int idx = tid; idx < 256; idx += NTH)
        Out[idx] = t16[(idx >> 4) * 17 + (idx & 15)].x;
}

// ---------------- second order, single-filter (N=128 only) ----------------
template<int N, int LOGN, int R, int NTH>
__global__ void __launch_bounds__(NTH) k_second(
    const float2* __restrict__ Bin,
    const float* __restrict__ psi, const float* __restrict__ phi,
    float* __restrict__ S, const float2* __restrict__ gtw, int chBase)
{
    extern __shared__ float2 dsh[];
    constexpr int P = N + 1;
    constexpr int M1 = N * R;
    float2* sh   = dsh;
    float2* tws  = sh + N * P;
    float2* tw16 = tws + N / 2;
    float2* t16  = tw16 + 8;
    int tid = threadIdx.x;
    load_tw<N, NTH>(tws, gtw, tid);
    for (int k = tid; k < 8; k += NTH) tw16[k] = gtw[k * 16];
    int o2 = blockIdx.x;
    int o1 = o2 >> 3, l2 = o2 & 7;
    const float2* I = Bin + (long)o1 * M1 * M1;
    const float*  F = psi + (long)l2 * M1 * M1;
    const float fs = 1.0f / ((float)M1 * (float)M1);
    for (int idx = tid; idx < N * N; idx += NTH) {
        int u = idx >> LOGN, v = idx & (N - 1);
        float sx = 0.0f, sy = 0.0f;
        #pragma unroll
        for (int s1 = 0; s1 < R; s1++) {
            fold_term<R>(I + (long)(u * R + s1) * M1 + v * R,
                         F + (long)(u * R + s1) * M1 + v * R, sx, sy);
        }
        sh[u * P + v] = make_float2(sx * fs, sy * fs);
    }
    __syncthreads();
    fft_inv<N, LOGN, N, LOGN, NTH, false>(sh, 1, P, tws, tid);
    fft_inv<N, LOGN, N, LOGN, NTH, true >(sh, P, 1, tws, tid);
    for (int idx = tid; idx < N * N; idx += NTH) {
        int u = idx >> LOGN, v = idx & (N - 1);
        float2 z = sh[u * P + v];
        sh[u * P + v] = make_float2(sqrtf(z.x * z.x + z.y * z.y), 0.0f);
    }
    __syncthreads();
    fft_fwd<N, LOGN, N, LOGN, NTH, false>(sh, 1, P, tws, tid);
    fft_fwd<N, LOGN, N, LOGN, NTH, true >(sh, P, 1, tws, tid);
    const float ps = 1.0f / ((float)N * (float)N);
    constexpr int R2 = N / 16;
    for (int idx = tid; idx < 256; idx += NTH) {
        int u = idx >> 4, v = idx & 15;
        float sx = 0.0f, sy = 0.0f;
        for (int s1 = 0; s1 < R2; s1++) {
            int U = u * R2 + s1;
            #pragma unroll 4
            for (int s2 = 0; s2 < R2; s2++) {
                int V = v * R2 + s2;
                float f = phi[U * N + V];
                float2 z = sh[U * P + V];
                sx += z.x * f;
                sy += z.y * f;
            }
        }
        t16[u * 17 + v] = make_float2(sx * ps, sy * ps);
    }
    __syncthreads();
    fft_inv<16, 4, 16, 4, NTH, false>(t16, 1, 17, tw16, tid);
    fft_inv<16, 4, 16, 4, NTH, true >(t16, 17, 1, tw16, tid);
    int b = o2 >> 6;
    int c = chBase + (o2 & 63);
    float* Out = S + ((long)b * 417 + c) * 256;
    for (int idx = tid; idx < 256; idx += NTH)
        Out[idx] = t16[(idx >> 4) * 17 + (idx & 15)].x;
}

// ---------------- second order, multi-tile (share B reads across TILES filters) ----------------
template<int N, int LOGN, int R, int TILES, int NTH>
__global__ void __launch_bounds__(NTH) k_second_mt(
    const float2* __restrict__ Bin,
    const float* __restrict__ psi, const float* __restrict__ phi,
    float* __restrict__ S, const float2* __restrict__ gtw, int chBase)
{
    extern __shared__ float2 dsh[];
    constexpr int P = N + 1;
    constexpr int M1 = N * R;
    constexpr int TSTR = N * P;
    float2* sh   = dsh;                        // TILES * TSTR
    float2* t16  = sh + TILES * TSTR;          // TILES * 272
    float2* tws  = t16 + TILES * 272;
    float2* tw16 = tws + N / 2;
    int tid = threadIdx.x;
    load_tw<N, NTH>(tws, gtw, tid);
    for (int k = tid; k < 8; k += NTH) tw16[k] = gtw[k * 16];
    constexpr int GRP = 8 / TILES;
    int o1 = blockIdx.x / GRP;
    int l2base = (blockIdx.x % GRP) * TILES;
    const float2* I = Bin + (long)o1 * M1 * M1;
    const float fs = 1.0f / ((float)M1 * (float)M1);
    // fold: load each B chunk once, use for TILES filters
    for (int idx = tid; idx < N * N; idx += NTH) {
        int u = idx >> LOGN, v = idx & (N - 1);
        float accx[TILES], accy[TILES];
        #pragma unroll
        for (int t = 0; t < TILES; t++) { accx[t] = 0.0f; accy[t] = 0.0f; }
        #pragma unroll
        for (int s1 = 0; s1 < R; s1++) {
            const float2* Ir = I + (long)(u * R + s1) * M1 + v * R;
            float4 bz[R / 2];
            #pragma unroll
            for (int k = 0; k < R / 2; k++) bz[k] = ((const float4*)Ir)[k];
            #pragma unroll
            for (int t = 0; t < TILES; t++) {
                const float* Fr = psi + (long)(l2base + t) * M1 * M1
                                      + (long)(u * R + s1) * M1 + v * R;
                if (R == 2) {
                    float2 f = *(const float2*)Fr;
                    accx[t] += bz[0].x * f.x + bz[0].z * f.y;
                    accy[t] += bz[0].y * f.x + bz[0].w * f.y;
                } else {
                    #pragma unroll
                    for (int k2 = 0; k2 < R / 4; k2++) {
                        float4 f = ((const float4*)Fr)[k2];
                        accx[t] += bz[2 * k2].x * f.x + bz[2 * k2].z * f.y
                                 + bz[2 * k2 + 1].x * f.z + bz[2 * k2 + 1].z * f.w;
                        accy[t] += bz[2 * k2].y * f.x + bz[2 * k2].w * f.y
                                 + bz[2 * k2 + 1].y * f.z + bz[2 * k2 + 1].w * f.w;
                    }
                }
            }
        }
        #pragma unroll
        for (int t = 0; t < TILES; t++)
            sh[t * TSTR + u * P + v] = make_float2(accx[t] * fs, accy[t] * fs);
    }
    __syncthreads();
    fft_inv_mt<N, LOGN, TILES, TSTR, NTH, false>(sh, 1, P, tws, tid);
    fft_inv_mt<N, LOGN, TILES, TSTR, NTH, true >(sh, P, 1, tws, tid);
    for (int idx = tid; idx < TILES * N * N; idx += NTH) {
        int t = idx >> (2 * LOGN);
        int r2 = idx & (N * N - 1);
        int u = r2 >> LOGN, v = r2 & (N - 1);
        float2 z = sh[t * TSTR + u * P + v];
        sh[t * TSTR + u * P + v] = make_float2(sqrtf(z.x * z.x + z.y * z.y), 0.0f);
    }
    __syncthreads();
    fft_fwd_mt<N, LOGN, TILES, TSTR, NTH, false>(sh, 1, P, tws, tid);
    fft_fwd_mt<N, LOGN, TILES, TSTR, NTH, true >(sh, P, 1, tws, tid);
    const float ps = 1.0f / ((float)N * (float)N);
    constexpr int R2 = N / 16;
    for (int idx = tid; idx < TILES * 256; idx += NTH) {
        int t = idx >> 8;
        int r2 = idx & 255;
        int u = r2 >> 4, v = r2 & 15;
        float sx = 0.0f, sy = 0.0f;
        #pragma unroll
        for (int s1 = 0; s1 < R2; s1++) {
            int U = u * R2 + s1;
            #pragma unroll
            for (int s2 = 0; s2 < R2; s2++) {
                int V = v * R2 + s2;
                float f = phi[U * N + V];
                float2 z = sh[t * TSTR + U * P + V];
                sx += z.x * f;
                sy += z.y * f;
            }
        }
        t16[t * 272 + u * 17 + v] = make_float2(sx * ps, sy * ps);
    }
    __syncthreads();
    fft_inv_mt<16, 4, TILES, 272, NTH, false>(t16, 1, 17, tw16, tid);
    fft_inv_mt<16, 4, TILES, 272, NTH, true >(t16, 17, 1, tw16, tid);
    int b = o1 >> 3;
    int cb = chBase + (o1 & 7) * 8 + l2base;
    for (int idx = tid; idx < TILES * 256; idx += NTH) {
        int t = idx >> 8;
        int r2 = idx & 255;
        float* Out = S + ((long)b * 417 + cb + t) * 256;
        Out[r2] = t16[t * 272 + (r2 >> 4) * 17 + (r2 & 15)].x;
    }
}

// ---------------- MLP ----------------
__global__ void __launch_bounds__(256) kgemm1(
    const float* __restrict__ S, const float* __restrict__ W, float* __restrict__ part)
{
    const int K = 106752, Nn = 1024, Kc = 834;
    int tid = threadIdx.x;
    int j = (blockIdx.x * 256 + tid) * 2;
    int k0 = blockIdx.y * Kc;
    __shared__ float ssh[16 * 64];
    float accx[16], accy[16];
    #pragma unroll
    for (int b = 0; b < 16; b++) { accx[b] = 0.0f; accy[b] = 0.0f; }
    for (int kt = 0; kt < Kc; kt += 64) {
        int nk = min(64, Kc - kt);
        __syncthreads();
        for (int i = tid; i < 16 * 64; i += 256) {
            int b = i >> 6, kk = i & 63;
            ssh[i] = (kk < nk) ? S[(long)b * K + k0 + kt + kk] : 0.0f;
        }
        __syncthreads();
        for (int kk = 0; kk < nk; kk++) {
            int k = k0 + kt + kk;
            float2 w = *(const float2*)(W + (long)k * Nn + j);
            #pragma unroll
            for (int b = 0; b < 16; b++) {
                float s = ssh[b * 64 + kk];
                accx[b] += s * w.x;
                accy[b] += s * w.y;
            }
        }
    }
    float* P = part + ((long)blockIdx.y * Nn + j) * 16;
    #pragma unroll
    for (int b = 0; b < 16; b++) { P[b] = accx[b]; P[b + 16] = accy[b]; }
}

__global__ void kred1(const float* __restrict__ part, const float* __restrict__ bias,
                      const float* __restrict__ g, const float* __restrict__ bb,
                      const float* __restrict__ mm, const float* __restrict__ vv,
                      float* __restrict__ h1)
{
    int id = blockIdx.x * 256 + threadIdx.x;
    if (id >= 16384) return;
    int j = id >> 4, b = id & 15;
    float s = 0.0f;
    for (int ks = 0; ks < 128; ks++) s += part[((long)ks * 1024 + j) * 16 + b];
    float z = s + bias[j];
    z = fmaxf(z, 0.0f);
    h1[b * 1024 + j] = (z - mm[j]) * rsqrtf(vv[j] + 1e-5f) * g[j] + bb[j];
}

__global__ void kfc_bn(const float* __restrict__ h, const float* __restrict__ W,
                       const float* __restrict__ bias, const float* __restrict__ g,
                       const float* __restrict__ bb, const float* __restrict__ mm,
                       const float* __restrict__ vv, float* __restrict__ out,
                       int K, int N)
{
    int id = blockIdx.x * blockDim.x + threadIdx.x;
    if (id >= 16 * N) return;
    int b = id / N, j = id - (id / N) * N;
    float acc = 0.0f;
    for (int k = 0; k < K; k++) acc += h[b * K + k] * W[(long)k * N + j];
    float z = acc + bias[j];
    z = fmaxf(z, 0.0f);
    out[b * N + j] = (z - mm[j]) * rsqrtf(vv[j] + 1e-5f) * g[j] + bb[j];
}

__global__ void kfc4(const float* __restrict__ h, const float* __restrict__ W,
                     const float* __restrict__ bias, float* __restrict__ out)
{
    __shared__ float red[128];
    int b = blockIdx.x, t = threadIdx.x;
    red[t] = h[b * 128 + t] * W[t];
    __syncthreads();
    for (int s = 64; s > 0; s >>= 1) {
        if (t < s) red[t] += red[t + s];
        __syncthreads();
    }
    if (t == 0) out[b] = red[0] + bias[0];
}

// ---------------- launch ----------------
extern "C" void kernel_launch(void* const* d_in, const int* in_sizes, int n_in,
                              void* d_out, int out_size)
{
    const float* x    = (const float*)d_in[0];
    const float* w1   = (const float*)d_in[1];
    const float* b1   = (const float*)d_in[2];
    const float* bn1g = (const float*)d_in[3];
    const float* bn1b = (const float*)d_in[4];
    const float* bn1m = (const float*)d_in[5];
    const float* bn1v = (const float*)d_in[6];
    const float* w2   = (const float*)d_in[7];
    const float* b2   = (const float*)d_in[8];
    const float* bn2g = (const float*)d_in[9];
    const float* bn2b = (const float*)d_in[10];
    const float* bn2m = (const float*)d_in[11];
    const float* bn2v = (const float*)d_in[12];
    const float* w3   = (const float*)d_in[13];
    const float* b3   = (const float*)d_in[14];
    const float* bn3g = (const float*)d_in[15];
    const float* bn3b = (const float*)d_in[16];
    const float* bn3m = (const float*)d_in[17];
    const float* bn3v = (const float*)d_in[18];
    const float* w4   = (const float*)d_in[19];
    const float* b4   = (const float*)d_in[20];

    float2 *Xf, *A, *B, *tw;
    float *S, *psi, *phi, *part, *h1, *h2, *h3;
    cudaGetSymbolAddress((void**)&Xf,  g_Xf);
    cudaGetSymbolAddress((void**)&A,   g_A);
    cudaGetSymbolAddress((void**)&B,   g_B);
    cudaGetSymbolAddress((void**)&S,   g_S);
    cudaGetSymbolAddress((void**)&psi, g_psi);
    cudaGetSymbolAddress((void**)&phi, g_phi);
    cudaGetSymbolAddress((void**)&tw,  g_tw);
    cudaGetSymbolAddress((void**)&part,g_part);
    cudaGetSymbolAddress((void**)&h1,  g_h1);
    cudaGetSymbolAddress((void**)&h2,  g_h2);
    cudaGetSymbolAddress((void**)&h3,  g_h3);

    const int SM128  = (128 * 129 + 64 + 8 + 272) * 8;
    const int SMC    = (256 * 17 + 128) * 8;
    const int SM64f  = (64 * 65 + 32 + 8 + 272) * 8;
    const int SM32f  = (32 * 33 + 16 + 8 + 272) * 8;
    const int SMT32  = (8 * 32 * 33 + 8 * 272 + 16 + 8) * 8;    // 85184
    const int SMT64  = (4 * 64 * 65 + 4 * 272 + 32 + 8) * 8;    // 142144

    cudaFuncSetAttribute(k_first_small<128, 7, 512>,
                         cudaFuncAttributeMaxDynamicSharedMemorySize, SM128);
    cudaFuncSetAttribute(k_second<128, 7, 2, 512>,
                         cudaFuncAttributeMaxDynamicSharedMemorySize, SM128);
    cudaFuncSetAttribute(k_second_mt<32, 5, 8, 8, 256>,
                         cudaFuncAttributeMaxDynamicSharedMemorySize, SMT32);
    cudaFuncSetAttribute(k_second_mt<32, 5, 4, 8, 256>,
                         cudaFuncAttributeMaxDynamicSharedMemorySize, SMT32);
    cudaFuncSetAttribute(k_second_mt<32, 5, 2, 8, 256>,
                         cudaFuncAttributeMaxDynamicSharedMemorySize, SMT32);
    cudaFuncSetAttribute(k_second_mt<64, 6, 4, 4, 512>,
                         cudaFuncAttributeMaxDynamicSharedMemorySize, SMT64);
    cudaFuncSetAttribute(k_second_mt<64, 6, 2, 4, 512>,
                         cudaFuncAttributeMaxDynamicSharedMemorySize, SMT64);

    const long psiR0[4] = {0, 8L * 65536, 16L * 65536, 24L * 65536};
    const long psiR1j1 = 4L * 8 * 65536;
    const long psiR1j2 = 4L * 8 * 65536 + 8L * 16384;
    const long psiR2j1 = 4L * 8 * 65536 + 16L * 16384;
    const long phiOff[4] = {0, 65536, 81920, 86016};

    kgen_psi<<<56, 256>>>(psi);
    kgen_phi<<<4, 256>>>(phi);
    kgen_tw<<<1, 128>>>(tw);

    // forward FFT of input
    kfwd_rows_real<<<1024, 256>>>(x, Xf, tw);
    kfwd_cols256<<<256, 256, SMC>>>(Xf, tw);

    // s0
    kphi16<<<16, 256>>>(Xf, phi, S, tw, 0, 1);

    // ---- j1 = 0 (full-res path) ----
    kfilt_rows<<<8192, 256>>>(Xf, psi, A, tw);
    kcols_mod256<<<2048, 256, SMC>>>(A, B, tw);
    kfwd_rows<<<8192, 256>>>(B, tw);
    kphi16<<<128, 256>>>(B, phi, S, tw, 1, 8);
    k_second<128, 7, 2, 512><<<1024, 512, SM128>>>(B, psi + psiR0[1], phi + phiOff[1], S, tw, 33);
    k_second_mt<64, 6, 4, 4, 512><<<256, 512, SMT64>>>(B, psi + psiR0[2], phi + phiOff[2], S, tw, 97);
    k_second_mt<32, 5, 8, 8, 256><<<128, 256, SMT32>>>(B, psi + psiR0[3], phi + phiOff[3], S, tw, 161);

    // ---- j1 = 1 ----
    k_first_small<128, 7, 512><<<128, 512, SM128>>>(Xf, psi + psiR0[1], phi + phiOff[1], B, S, tw, 9);
    k_second_mt<64, 6, 2, 4, 512><<<256, 512, SMT64>>>(B, psi + psiR1j1, phi + phiOff[2], S, tw, 225);
    k_second_mt<32, 5, 4, 8, 256><<<128, 256, SMT32>>>(B, psi + psiR1j2, phi + phiOff[3], S, tw, 289);

    // ---- j1 = 2 ----
    k_first_small<64, 6, 256><<<128, 256, SM64f>>>(Xf, psi + psiR0[2], phi + phiOff[2], B, S, tw, 17);
    k_second_mt<32, 5, 2, 8, 256><<<128, 256, SMT32>>>(B, psi + psiR2j1, phi + phiOff[3], S, tw, 353);

    // ---- j1 = 3 ----
    k_first_small<32, 5, 128><<<128, 128, SM32f>>>(Xf, psi + psiR0[3], phi + phiOff[3], B, S, tw, 25);

    // MLP
    dim3 g1(2, 128);
    kgemm1<<<g1, 256>>>(S, w1, part);
    kred1<<<64, 256>>>(part, b1, bn1g, bn1b, bn1m, bn1v, h1);
    kfc_bn<<<(16 * 512 + 255) / 256, 256>>>(h1, w2, b2, bn2g, bn2b, bn2m, bn2v, h2, 1024, 512);
    kfc_bn<<<(16 * 128 + 255) / 256, 256>>>(h2, w3, b3, bn3g, bn3b, bn3m, bn3v, h3, 512, 128);
    kfc4<<<16, 128>>>(h3, w4, b4, (float*)d_out);
}

// round 16
// speedup vs baseline: 1.0435x; 1.0435x over previous
#include <cuda_runtime.h>
#include <math.h>

#define PI_F 3.14159265358979323846f

// ---------------- device globals ----------------
__device__ float2 g_Xf[16 * 256 * 256];
__device__ float2 g_A [128 * 256 * 256];
__device__ float2 g_B [128 * 256 * 256];
__device__ float2 g_B1[128 * 128 * 128];
__device__ float2 g_B2[128 * 64 * 64];
__device__ float2 g_B3[128 * 32 * 32];
__device__ float  g_S [16 * 417 * 256];
__device__ float  g_psi[2392064];
__device__ float  g_phi[87040];
__device__ float2 g_tw[128];
__device__ float  g_part[128 * 1024 * 16];
__device__ float  g_h1[16 * 1024];
__device__ float  g_h2[16 * 512];
__device__ float  g_h3[16 * 128];

__device__ __forceinline__ float2 cmul(float2 a, float2 b)
{
    return make_float2(a.x * b.x - a.y * b.y, a.x * b.y + a.y * b.x);
}

// vectorized fold: R contiguous complex terms * R contiguous filter floats
template<int R>
__device__ __forceinline__ void fold_term(const float2* __restrict__ Ir,
                                          const float* __restrict__ Fr,
                                          float& sx, float& sy)
{
    if (R == 2) {
        float4 z = *(const float4*)Ir;
        float2 f = *(const float2*)Fr;
        sx += z.x * f.x + z.z * f.y;
        sy += z.y * f.x + z.w * f.y;
    } else {
        #pragma unroll
        for (int s = 0; s < R / 4; s++) {
            float4 a = ((const float4*)Ir)[2 * s];
            float4 b = ((const float4*)Ir)[2 * s + 1];
            float4 f = ((const float4*)Fr)[s];
            sx += a.x * f.x + a.z * f.y + b.x * f.z + b.z * f.w;
            sy += a.y * f.x + a.w * f.y + b.y * f.z + b.w * f.w;
        }
    }
}

// ---------------- DIF (fwd) / DIT (inv), radix-2^2, no bit-reversal ----------------
template<int N, int LOGN, int NFFT, int LOGNF, int NTH, bool CMAJ>
__device__ __forceinline__ void fft_inv(float2* sh, int stride, int fstride,
                                        const float2* tw, int tid)
{
    constexpr int HTOT = NFFT * (N >> 1);
    constexpr int TOT4 = NFFT * (N >> 2);
    int s = 1;
    if (LOGN & 1) {
        for (int q = 0; q < (HTOT + NTH - 1) / NTH; q++) {
            int w = tid + q * NTH;
            if ((HTOT % NTH) && w >= HTOT) break;
            int f, r;
            if (CMAJ) { f = w & (NFFT - 1); r = w >> LOGNF; }
            else      { f = w >> (LOGN - 1); r = w & ((N >> 1) - 1); }
            float2* p = sh + f * fstride;
            int i0 = (2 * r) * stride;
            float2 a = p[i0], b = p[i0 + stride];
            p[i0]          = make_float2(a.x + b.x, a.y + b.y);
            p[i0 + stride] = make_float2(a.x - b.x, a.y - b.y);
        }
        __syncthreads();
        s = 2;
    }
    for (; s < LOGN; s += 2) {
        for (int q = 0; q < (TOT4 + NTH - 1) / NTH; q++) {
            int w = tid + q * NTH;
            if ((TOT4 % NTH) && w >= TOT4) break;
            int f, r;
            if (CMAJ) { f = w & (NFFT - 1); r = w >> LOGNF; }
            else      { f = w >> (LOGN - 2); r = w & ((N >> 2) - 1); }
            int h = 1 << (s - 1);
            int j = r & (h - 1);
            int base = (r >> (s - 1)) << (s + 1);
            float2 W1 = tw[j << (LOGN - s)];
            float2 W2 = tw[j << (LOGN - s - 1)];
            float2* p = sh + f * fstride;
            int hs = h * stride;
            int i0 = (base + j) * stride;
            float2 x0 = p[i0], x1 = p[i0 + hs], x2 = p[i0 + 2 * hs], x3 = p[i0 + 3 * hs];
            float2 t1 = cmul(W1, x1), t3 = cmul(W1, x3);
            float2 y0 = make_float2(x0.x + t1.x, x0.y + t1.y);
            float2 y1 = make_float2(x0.x - t1.x, x0.y - t1.y);
            float2 y2 = make_float2(x2.x + t3.x, x2.y + t3.y);
            float2 y3 = make_float2(x2.x - t3.x, x2.y - t3.y);
            float2 u = cmul(W2, y2);
            float2 iW2 = make_float2(-W2.y, W2.x);
            float2 v = cmul(iW2, y3);
            p[i0]          = make_float2(y0.x + u.x, y0.y + u.y);
            p[i0 + 2 * hs] = make_float2(y0.x - u.x, y0.y - u.y);
            p[i0 + hs]     = make_float2(y1.x + v.x, y1.y + v.y);
            p[i0 + 3 * hs] = make_float2(y1.x - v.x, y1.y - v.y);
        }
        __syncthreads();
    }
}

template<int N, int LOGN, int NFFT, int LOGNF, int NTH, bool CMAJ>
__device__ __forceinline__ void fft_fwd(float2* sh, int stride, int fstride,
                                        const float2* tw, int tid)
{
    constexpr int HTOT = NFFT * (N >> 1);
    constexpr int TOT4 = NFFT * (N >> 2);
    constexpr int SLO = (LOGN & 1) ? 3 : 2;
    for (int s = LOGN; s >= SLO; s -= 2) {
        for (int q = 0; q < (TOT4 + NTH - 1) / NTH; q++) {
            int w = tid + q * NTH;
            if ((TOT4 % NTH) && w >= TOT4) break;
            int f, r;
            if (CMAJ) { f = w & (NFFT - 1); r = w >> LOGNF; }
            else      { f = w >> (LOGN - 2); r = w & ((N >> 2) - 1); }
            int h = 1 << (s - 2);
            int j = r & (h - 1);
            int base = (r >> (s - 2)) << s;
            float2 W2 = tw[j << (LOGN - s)];
            float2 W1 = tw[j << (LOGN - s + 1)];
            float2 W2c = make_float2(W2.x, -W2.y);
            float2 W1c = make_float2(W1.x, -W1.y);
            float2 miW2c = make_float2(-W2.y, -W2.x);
            float2* p = sh + f * fstride;
            int hs = h * stride;
            int i0 = (base + j) * stride;
            float2 x0 = p[i0], x1 = p[i0 + hs], x2 = p[i0 + 2 * hs], x3 = p[i0 + 3 * hs];
            float2 p0 = make_float2(x0.x + x2.x, x0.y + x2.y);
            float2 q2 = make_float2(x0.x - x2.x, x0.y - x2.y);
            float2 p1 = make_float2(x1.x + x3.x, x1.y + x3.y);
            float2 q3 = make_float2(x1.x - x3.x, x1.y - x3.y);
            float2 t2 = cmul(W2c, q2);
            float2 t3 = cmul(miW2c, q3);
            float2 d01 = make_float2(p0.x - p1.x, p0.y - p1.y);
            float2 d23 = make_float2(t2.x - t3.x, t2.y - t3.y);
            p[i0]          = make_float2(p0.x + p1.x, p0.y + p1.y);
            p[i0 + hs]     = cmul(W1c, d01);
            p[i0 + 2 * hs] = make_float2(t2.x + t3.x, t2.y + t3.y);
            p[i0 + 3 * hs] = cmul(W1c, d23);
        }
        __syncthreads();
    }
    if (LOGN & 1) {
        for (int q = 0; q < (HTOT + NTH - 1) / NTH; q++) {
            int w = tid + q * NTH;
            if ((HTOT % NTH) && w >= HTOT) break;
            int f, r;
            if (CMAJ) { f = w & (NFFT - 1); r = w >> LOGNF; }
            else      { f = w >> (LOGN - 1); r = w & ((N >> 1) - 1); }
            float2* p = sh + f * fstride;
            int i0 = (2 * r) * stride;
            float2 a = p[i0], b = p[i0 + stride];
            p[i0]          = make_float2(a.x + b.x, a.y + b.y);
            p[i0 + stride] = make_float2(a.x - b.x, a.y - b.y);
        }
        __syncthreads();
    }
}

template<int N, int NTH>
__device__ __forceinline__ void load_tw(float2* tws, const float2* gtw, int tid)
{
    for (int k = tid; k < N / 2; k += NTH) tws[k] = gtw[k * (256 / N)];
}

// ---------------- filter / table generation (bit-reversed frequency layout) ----------------
__global__ void kgen_tw(float2* tw)
{
    int k = threadIdx.x;
    if (k < 128) {
        float s, c;
        __sincosf(2.0f * PI_F * (float)k / 256.0f, &s, &c);
        tw[k] = make_float2(c, s);
    }
}

__global__ void kgen_psi(float* __restrict__ psi)
{
    int fi = blockIdx.x;
    int bank = fi >> 3;
    int l = fi & 7;
    int m, js, logm;
    long off;
    if (bank < 4)      { m = 256; js = bank; off = (long)bank * 8 * 65536; logm = 8; }
    else if (bank == 4){ m = 128; js = 1;    off = 4L * 8 * 65536;               logm = 7; }
    else if (bank == 5){ m = 128; js = 2;    off = 4L * 8 * 65536 + 8L * 16384;  logm = 7; }
    else               { m = 64;  js = 1;    off = 4L * 8 * 65536 + 16L * 16384; logm = 6; }
    float* F = psi + off + (long)l * m * m;
    float sigma = 0.8f * (float)(1 << js);
    float xi = (3.0f * PI_F / 4.0f) / (float)(1 << js);
    float th = (float)l * PI_F / 8.0f;
    float st, ct;
    __sincosf(th, &st, &ct);
    float s2 = 0.5f * sigma * sigma;
    float beta = expf(-s2 * xi * xi);
    float mx = 0.0f;
    int tid = threadIdx.x;
    int half = m >> 1;
    for (int idx = tid; idx < m * m; idx += 256) {
        int pu = idx / m, pv = idx - (idx / m) * m;
        int u = (int)(__brev((unsigned)pu) >> (32 - logm));
        int v = (int)(__brev((unsigned)pv) >> (32 - logm));
        float kx = 2.0f * PI_F * ((u < half) ? (float)u : (float)(u - m)) / (float)m;
        float ky = 2.0f * PI_F * ((v < half) ? (float)v : (float)(v - m)) / (float)m;
        float w1 =  kx * ct + ky * st;
        float w2 = -kx * st + ky * ct;
        float sw2 = 0.5f * w2;
        float a   = expf(-s2 * ((w1 - xi) * (w1 - xi) + sw2 * sw2));
        float env = expf(-s2 * (w1 * w1 + sw2 * sw2));
        float fv = a - beta * env;
        F[idx] = fv;
        mx = fmaxf(mx, fv);
    }
    __shared__ float red[256];
    red[tid] = mx;
    __syncthreads();
    for (int s = 128; s > 0; s >>= 1) {
        if (tid < s) red[tid] = fmaxf(red[tid], red[tid + s]);
        __syncthreads();
    }
    float inv = 1.0f / fmaxf(red[0], 1e-12f);
    for (int idx = tid; idx < m * m; idx += 256) F[idx] *= inv;
}

__global__ void kgen_phi(float* __restrict__ phi)
{
    int r = blockIdx.x;
    int m = 256 >> r;
    int logm = 8 - r;
    long off = (r == 0) ? 0 : (r == 1) ? 65536 : (r == 2) ? 81920 : 86016;
    float sigma = 0.8f * (float)(1 << (4 - r));
    float s2 = 0.5f * sigma * sigma;
    float* F = phi + off;
    int half = m >> 1;
    for (int idx = threadIdx.x; idx < m * m; idx += 256) {
        int pu = idx / m, pv = idx - (idx / m) * m;
        int u = (int)(__brev((unsigned)pu) >> (32 - logm));
        int v = (int)(__brev((unsigned)pv) >> (32 - logm));
        float kx = 2.0f * PI_F * ((u < half) ? (float)u : (float)(u - m)) / (float)m;
        float ky = 2.0f * PI_F * ((v < half) ? (float)v : (float)(v - m)) / (float)m;
        F[idx] = expf(-s2 * (kx * kx + ky * ky));
    }
}

// ---------------- 256-size (j1=0) path ----------------
__global__ void __launch_bounds__(256) kfwd_rows_real(
    const float* __restrict__ x, float2* __restrict__ Xf, const float2* __restrict__ gtw)
{
    __shared__ float2 sh[1024];
    __shared__ float2 tws[128];
    int tid = threadIdx.x;
    load_tw<256, 256>(tws, gtw, tid);
    const float4* X4 = (const float4*)(x + (long)blockIdx.x * 1024);
    {
        float4 v = X4[tid];
        sh[4 * tid + 0] = make_float2(v.x, 0.0f);
        sh[4 * tid + 1] = make_float2(v.y, 0.0f);
        sh[4 * tid + 2] = make_float2(v.z, 0.0f);
        sh[4 * tid + 3] = make_float2(v.w, 0.0f);
    }
    __syncthreads();
    fft_fwd<256, 8, 4, 2, 256, false>(sh, 1, 256, tws, tid);
    float4* O4 = (float4*)(Xf + (long)blockIdx.x * 1024);
    const float4* S4 = (const float4*)sh;
    O4[tid] = S4[tid];
    O4[tid + 256] = S4[tid + 256];
}

__global__ void __launch_bounds__(256) kfwd_cols256(
    float2* __restrict__ d, const float2* __restrict__ gtw)
{
    extern __shared__ float2 dsh[];
    float2* sh = dsh;
    float2* tws = dsh + 256 * 17;
    int tid = threadIdx.x;
    load_tw<256, 256>(tws, gtw, tid);
    int img = blockIdx.x >> 4, c0 = (blockIdx.x & 15) << 4;
    float2* D = d + (long)img * 65536 + c0;
    for (int idx = tid; idx < 2048; idx += 256) {
        int i = idx >> 3, c = (idx & 7) * 2;
        float4 v = *(const float4*)(D + (long)i * 256 + c);
        sh[i * 17 + c]     = make_float2(v.x, v.y);
        sh[i * 17 + c + 1] = make_float2(v.z, v.w);
    }
    __syncthreads();
    fft_fwd<256, 8, 16, 4, 256, true>(sh, 17, 1, tws, tid);
    for (int idx = tid; idx < 2048; idx += 256) {
        int i = idx >> 3, c = (idx & 7) * 2;
        float2 a = sh[i * 17 + c], b = sh[i * 17 + c + 1];
        *(float4*)(D + (long)i * 256 + c) = make_float4(a.x, a.y, b.x, b.y);
    }
}

__global__ void __launch_bounds__(256) kfilt_rows(
    const float2* __restrict__ Xf, const float* __restrict__ psi,
    float2* __restrict__ A, const float2* __restrict__ gtw)
{
    __shared__ float2 sh[1024];
    __shared__ float2 tws[128];
    int tid = threadIdx.x;
    load_tw<256, 256>(tws, gtw, tid);
    int o = blockIdx.x >> 6, rg = blockIdx.x & 63;
    int img = o >> 3, l = o & 7;
    const float4* I4 = (const float4*)(Xf + (long)img * 65536 + rg * 1024);
    const float2* F2 = (const float2*)(psi + (long)l * 65536 + rg * 1024);
    const float sc = 1.0f / 256.0f;
    for (int i = tid; i < 512; i += 256) {
        float4 z = I4[i];
        float2 f = F2[i];
        sh[2 * i]     = make_float2(z.x * f.x * sc, z.y * f.x * sc);
        sh[2 * i + 1] = make_float2(z.z * f.y * sc, z.w * f.y * sc);
    }
    __syncthreads();
    fft_inv<256, 8, 4, 2, 256, false>(sh, 1, 256, tws, tid);
    float4* O4 = (float4*)(A + (long)o * 65536 + rg * 1024);
    const float4* S4 = (const float4*)sh;
    O4[tid] = S4[tid];
    O4[tid + 256] = S4[tid + 256];
}

__global__ void __launch_bounds__(256) kcols_mod256(
    const float2* __restrict__ in, float2* __restrict__ out, const float2* __restrict__ gtw)
{
    extern __shared__ float2 dsh[];
    float2* sh = dsh;
    float2* tws = dsh + 256 * 17;
    int tid = threadIdx.x;
    load_tw<256, 256>(tws, gtw, tid);
    int img = blockIdx.x >> 4, c0 = (blockIdx.x & 15) << 4;
    const float2* I = in  + (long)img * 65536 + c0;
    float2*       O = out + (long)img * 65536 + c0;
    for (int idx = tid; idx < 2048; idx += 256) {
        int i = idx >> 3, c = (idx & 7) * 2;
        float4 v = *(const float4*)(I + (long)i * 256 + c);
        sh[i * 17 + c]     = make_float2(v.x, v.y);
        sh[i * 17 + c + 1] = make_float2(v.z, v.w);
    }
    __syncthreads();
    fft_inv<256, 8, 16, 4, 256, true>(sh, 17, 1, tws, tid);
    const float inv = 1.0f / 256.0f;
    for (int idx = tid; idx < 4096; idx += 256) {
        int i = idx >> 4, c = idx & 15;
        float2 z = sh[i * 17 + c];
        sh[i * 17 + c] = make_float2(sqrtf(z.x * z.x + z.y * z.y) * inv, 0.0f);
    }
    __syncthreads();
    fft_fwd<256, 8, 16, 4, 256, true>(sh, 17, 1, tws, tid);
    for (int idx = tid; idx < 2048; idx += 256) {
        int i = idx >> 3, c = (idx & 7) * 2;
        float2 a = sh[i * 17 + c], b = sh[i * 17 + c + 1];
        *(float4*)(O + (long)i * 256 + c) = make_float4(a.x, a.y, b.x, b.y);
    }
}

__global__ void __launch_bounds__(256) kfwd_rows(
    float2* __restrict__ d, const float2* __restrict__ gtw)
{
    __shared__ float2 sh[1024];
    __shared__ float2 tws[128];
    int tid = threadIdx.x;
    load_tw<256, 256>(tws, gtw, tid);
    float4* D4 = (float4*)(d + (long)blockIdx.x * 1024);
    float4* S4 = (float4*)sh;
    S4[tid] = D4[tid];
    S4[tid + 256] = D4[tid + 256];
    __syncthreads();
    fft_fwd<256, 8, 4, 2, 256, false>(sh, 1, 256, tws, tid);
    D4[tid] = S4[tid];
    D4[tid + 256] = S4[tid + 256];
}

// phi fold (256 -> 16) + 16x16 inverse FFT -> S
__global__ void __launch_bounds__(256) kphi16(
    const float2* __restrict__ in, const float* __restrict__ phi,
    float* __restrict__ S, const float2* __restrict__ gtw, int chBase, int CH)
{
    __shared__ float2 t16[16 * 17];
    __shared__ float2 tw16[8];
    int tid = threadIdx.x;
    if (tid < 8) tw16[tid] = gtw[tid * 16];
    int o = blockIdx.x;
    const float2* I = in + (long)o * 65536;
    const float ps = 1.0f / 65536.0f;
    int u = tid >> 4, v = tid & 15;
    float sx = 0.0f, sy = 0.0f;
    #pragma unroll 4
    for (int s1 = 0; s1 < 16; s1++) {
        const float2* Ir = I + (u * 16 + s1) * 256 + v * 16;
        const float*  Fr = phi + (u * 16 + s1) * 256 + v * 16;
        fold_term<16>(Ir, Fr, sx, sy);
    }
    t16[u * 17 + v] = make_float2(sx * ps, sy * ps);
    __syncthreads();
    fft_inv<16, 4, 16, 4, 256, false>(t16, 1, 17, tw16, tid);
    fft_inv<16, 4, 16, 4, 256, true >(t16, 17, 1, tw16, tid);
    int b = o / CH;
    int c = chBase + (o - b * CH);
    float* Out = S + ((long)b * 417 + c) * 256;
    Out[tid] = t16[u * 17 + v].x;
}

// ---------------- fused first-order small kernels ----------------
template<int N, int LOGN, int NTH>
__global__ void __launch_bounds__(NTH) k_first_small(
    const float2* __restrict__ Xf, const float* __restrict__ psi,
    const float* __restrict__ phi, float2* __restrict__ Bout,
    float* __restrict__ S, const float2* __restrict__ gtw, int chBase)
{
    extern __shared__ float2 dsh[];
    constexpr int P = N + 1;
    float2* sh   = dsh;
    float2* tws  = sh + N * P;
    float2* tw16 = tws + N / 2;
    float2* t16  = tw16 + 8;
    int tid = threadIdx.x;
    load_tw<N, NTH>(tws, gtw, tid);
    for (int k = tid; k < 8; k += NTH) tw16[k] = gtw[k * 16];
    int o = blockIdx.x;
    int img = o >> 3, l = o & 7;
    const float2* I = Xf + (long)img * 65536;
    const float*  F = psi + (long)l * 65536;
    constexpr int R = 256 / N;
    const float fs = 1.0f / 65536.0f;
    for (int idx = tid; idx < N * N; idx += NTH) {
        int u = idx >> LOGN, v = idx & (N - 1);
        float sx = 0.0f, sy = 0.0f;
        #pragma unroll
        for (int s1 = 0; s1 < R; s1++) {
            fold_term<R>(I + (long)(u * R + s1) * 256 + v * R,
                         F + (long)(u * R + s1) * 256 + v * R, sx, sy);
        }
        sh[u * P + v] = make_float2(sx * fs, sy * fs);
    }
    __syncthreads();
    fft_inv<N, LOGN, N, LOGN, NTH, false>(sh, 1, P, tws, tid);
    fft_inv<N, LOGN, N, LOGN, NTH, true >(sh, P, 1, tws, tid);
    for (int idx = tid; idx < N * N; idx += NTH) {
        int u = idx >> LOGN, v = idx & (N - 1);
        float2 z = sh[u * P + v];
        sh[u * P + v] = make_float2(sqrtf(z.x * z.x + z.y * z.y), 0.0f);
    }
    __syncthreads();
    fft_fwd<N, LOGN, N, LOGN, NTH, false>(sh, 1, P, tws, tid);
    fft_fwd<N, LOGN, N, LOGN, NTH, true >(sh, P, 1, tws, tid);
    float2* O = Bout + (long)o * N * N;
    for (int idx = tid; idx < N * N; idx += NTH) {
        int u = idx >> LOGN, v = idx & (N - 1);
        O[idx] = sh[u * P + v];
    }
    const float ps = 1.0f / ((float)N * (float)N);
    constexpr int R2 = N / 16;
    for (int idx = tid; idx < 256; idx += NTH) {
        int u = idx >> 4, v = idx & 15;
        float sx = 0.0f, sy = 0.0f;
        for (int s1 = 0; s1 < R2; s1++) {
            int U = u * R2 + s1;
            #pragma unroll 4
            for (int s2 = 0; s2 < R2; s2++) {
                int V = v * R2 + s2;
                float f = phi[U * N + V];
                float2 z = sh[U * P + V];
                sx += z.x * f;
                sy += z.y * f;
            }
        }
        t16[u * 17 + v] = make_float2(sx * ps, sy * ps);
    }
    __syncthreads();
    fft_inv<16, 4, 16, 4, NTH, false>(t16, 1, 17, tw16, tid);
    fft_inv<16, 4, 16, 4, NTH, true >(t16, 17, 1, tw16, tid);
    float* Out = S + ((long)img * 417 + chBase + l) * 256;
    for (int idx = tid; idx < 256; idx += NTH)
        Out[idx] = t16[(idx >> 4) * 17 + (idx & 15)].x;
}

// ---------------- second order ----------------
template<int N, int LOGN, int R, int NTH>
__global__ void __launch_bounds__(NTH) k_second(
    const float2* __restrict__ Bin,
    const float* __restrict__ psi, const float* __restrict__ phi,
    float* __restrict__ S, const float2* __restrict__ gtw, int chBase)
{
    extern __shared__ float2 dsh[];
    constexpr int P = N + 1;
    constexpr int M1 = N * R;
    float2* sh   = dsh;
    float2* tws  = sh + N * P;
    float2* tw16 = tws + N / 2;
    float2* t16  = tw16 + 8;
    int tid = threadIdx.x;
    load_tw<N, NTH>(tws, gtw, tid);
    for (int k = tid; k < 8; k += NTH) tw16[k] = gtw[k * 16];
    int o2 = blockIdx.x;
    int o1 = o2 >> 3, l2 = o2 & 7;
    const float2* I = Bin + (long)o1 * M1 * M1;
    const float*  F = psi + (long)l2 * M1 * M1;
    const float fs = 1.0f / ((float)M1 * (float)M1);
    for (int idx = tid; idx < N * N; idx += NTH) {
        int u = idx >> LOGN, v = idx & (N - 1);
        float sx = 0.0f, sy = 0.0f;
        #pragma unroll
        for (int s1 = 0; s1 < R; s1++) {
            fold_term<R>(I + (long)(u * R + s1) * M1 + v * R,
                         F + (long)(u * R + s1) * M1 + v * R, sx, sy);
        }
        sh[u * P + v] = make_float2(sx * fs, sy * fs);
    }
    __syncthreads();
    fft_inv<N, LOGN, N, LOGN, NTH, false>(sh, 1, P, tws, tid);
    fft_inv<N, LOGN, N, LOGN, NTH, true >(sh, P, 1, tws, tid);
    for (int idx = tid; idx < N * N; idx += NTH) {
        int u = idx >> LOGN, v = idx & (N - 1);
        float2 z = sh[u * P + v];
        sh[u * P + v] = make_float2(sqrtf(z.x * z.x + z.y * z.y), 0.0f);
    }
    __syncthreads();
    fft_fwd<N, LOGN, N, LOGN, NTH, false>(sh, 1, P, tws, tid);
    fft_fwd<N, LOGN, N, LOGN, NTH, true >(sh, P, 1, tws, tid);
    const float ps = 1.0f / ((float)N * (float)N);
    constexpr int R2 = N / 16;
    for (int idx = tid; idx < 256; idx += NTH) {
        int u = idx >> 4, v = idx & 15;
        float sx = 0.0f, sy = 0.0f;
        for (int s1 = 0; s1 < R2; s1++) {
            int U = u * R2 + s1;
            #pragma unroll 4
            for (int s2 = 0; s2 < R2; s2++) {
                int V = v * R2 + s2;
                float f = phi[U * N + V];
                float2 z = sh[U * P + V];
                sx += z.x * f;
                sy += z.y * f;
            }
        }
        t16[u * 17 + v] = make_float2(sx * ps, sy * ps);
    }
    __syncthreads();
    fft_inv<16, 4, 16, 4, NTH, false>(t16, 1, 17, tw16, tid);
    fft_inv<16, 4, 16, 4, NTH, true >(t16, 17, 1, tw16, tid);
    int b = o2 >> 6;
    int c = chBase + (o2 & 63);
    float* Out = S + ((long)b * 417 + c) * 256;
    for (int idx = tid; idx < 256; idx += NTH)
        Out[idx] = t16[(idx >> 4) * 17 + (idx & 15)].x;
}

// ---------------- MLP ----------------
__global__ void __launch_bounds__(256) kgemm1(
    const float* __restrict__ S, const float* __restrict__ W, float* __restrict__ part)
{
    const int K = 106752, Nn = 1024, Kc = 834;
    int tid = threadIdx.x;
    int j = (blockIdx.x * 256 + tid) * 2;
    int k0 = blockIdx.y * Kc;
    __shared__ float ssh[16 * 64];
    float accx[16], accy[16];
    #pragma unroll
    for (int b = 0; b < 16; b++) { accx[b] = 0.0f; accy[b] = 0.0f; }
    for (int kt = 0; kt < Kc; kt += 64) {
        int nk = min(64, Kc - kt);
        __syncthreads();
        for (int i = tid; i < 16 * 64; i += 256) {
            int b = i >> 6, kk = i & 63;
            ssh[i] = (kk < nk) ? S[(long)b * K + k0 + kt + kk] : 0.0f;
        }
        __syncthreads();
        for (int kk = 0; kk < nk; kk++) {
            int k = k0 + kt + kk;
            float2 w = *(const float2*)(W + (long)k * Nn + j);
            #pragma unroll
            for (int b = 0; b < 16; b++) {
                float s = ssh[b * 64 + kk];
                accx[b] += s * w.x;
                accy[b] += s * w.y;
            }
        }
    }
    float* P = part + ((long)blockIdx.y * Nn + j) * 16;
    #pragma unroll
    for (int b = 0; b < 16; b++) { P[b] = accx[b]; P[b + 16] = accy[b]; }
}

__global__ void kred1(const float* __restrict__ part, const float* __restrict__ bias,
                      const float* __restrict__ g, const float* __restrict__ bb,
                      const float* __restrict__ mm, const float* __restrict__ vv,
                      float* __restrict__ h1)
{
    int id = blockIdx.x * 256 + threadIdx.x;
    if (id >= 16384) return;
    int j = id >> 4, b = id & 15;
    float s = 0.0f;
    for (int ks = 0; ks < 128; ks++) s += part[((long)ks * 1024 + j) * 16 + b];
    float z = s + bias[j];
    z = fmaxf(z, 0.0f);
    h1[b * 1024 + j] = (z - mm[j]) * rsqrtf(vv[j] + 1e-5f) * g[j] + bb[j];
}

__global__ void kfc_bn(const float* __restrict__ h, const float* __restrict__ W,
                       const float* __restrict__ bias, const float* __restrict__ g,
                       const float* __restrict__ bb, const float* __restrict__ mm,
                       const float* __restrict__ vv, float* __restrict__ out,
                       int K, int N)
{
    int id = blockIdx.x * blockDim.x + threadIdx.x;
    if (id >= 16 * N) return;
    int b = id / N, j = id - (id / N) * N;
    float acc = 0.0f;
    for (int k = 0; k < K; k++) acc += h[b * K + k] * W[(long)k * N + j];
    float z = acc + bias[j];
    z = fmaxf(z, 0.0f);
    out[b * N + j] = (z - mm[j]) * rsqrtf(vv[j] + 1e-5f) * g[j] + bb[j];
}

__global__ void kfc4(const float* __restrict__ h, const float* __restrict__ W,
                     const float* __restrict__ bias, float* __restrict__ out)
{
    __shared__ float red[128];
    int b = blockIdx.x, t = threadIdx.x;
    red[t] = h[b * 128 + t] * W[t];
    __syncthreads();
    for (int s = 64; s > 0; s >>= 1) {
        if (t < s) red[t] += red[t + s];
        __syncthreads();
    }
    if (t == 0) out[b] = red[0] + bias[0];
}

// ---------------- launch ----------------
extern "C" void kernel_launch(void* const* d_in, const int* in_sizes, int n_in,
                              void* d_out, int out_size)
{
    const float* x    = (const float*)d_in[0];
    const float* w1   = (const float*)d_in[1];
    const float* b1   = (const float*)d_in[2];
    const float* bn1g = (const float*)d_in[3];
    const float* bn1b = (const float*)d_in[4];
    const float* bn1m = (const float*)d_in[5];
    const float* bn1v = (const float*)d_in[6];
    const float* w2   = (const float*)d_in[7];
    const float* b2   = (const float*)d_in[8];
    const float* bn2g = (const float*)d_in[9];
    const float* bn2b = (const float*)d_in[10];
    const float* bn2m = (const float*)d_in[11];
    const float* bn2v = (const float*)d_in[12];
    const float* w3   = (const float*)d_in[13];
    const float* b3   = (const float*)d_in[14];
    const float* bn3g = (const float*)d_in[15];
    const float* bn3b = (const float*)d_in[16];
    const float* bn3m = (const float*)d_in[17];
    const float* bn3v = (const float*)d_in[18];
    const float* w4   = (const float*)d_in[19];
    const float* b4   = (const float*)d_in[20];

    float2 *Xf, *A, *B, *B1, *B2, *B3, *tw;
    float *S, *psi, *phi, *part, *h1, *h2, *h3;
    cudaGetSymbolAddress((void**)&Xf,  g_Xf);
    cudaGetSymbolAddress((void**)&A,   g_A);
    cudaGetSymbolAddress((void**)&B,   g_B);
    cudaGetSymbolAddress((void**)&B1,  g_B1);
    cudaGetSymbolAddress((void**)&B2,  g_B2);
    cudaGetSymbolAddress((void**)&B3,  g_B3);
    cudaGetSymbolAddress((void**)&S,   g_S);
    cudaGetSymbolAddress((void**)&psi, g_psi);
    cudaGetSymbolAddress((void**)&phi, g_phi);
    cudaGetSymbolAddress((void**)&tw,  g_tw);
    cudaGetSymbolAddress((void**)&part,g_part);
    cudaGetSymbolAddress((void**)&h1,  g_h1);
    cudaGetSymbolAddress((void**)&h2,  g_h2);
    cudaGetSymbolAddress((void**)&h3,  g_h3);

    const int SM128 = (128 * 129 + 64 + 8 + 272) * 8;
    const int SMC   = (256 * 17 + 128) * 8;
    const int SM64  = (64 * 65 + 32 + 8 + 272) * 8;
    const int SM32  = (32 * 33 + 16 + 8 + 272) * 8;

    cudaFuncSetAttribute(k_first_small<128, 7, 512>,
                         cudaFuncAttributeMaxDynamicSharedMemorySize, SM128);
    cudaFuncSetAttribute(k_second<128, 7, 2, 512>,
                         cudaFuncAttributeMaxDynamicSharedMemorySize, SM128);

    // streams/events: created once on the (pre-capture) correctness call; only
    // launches + event record/wait happen during graph capture.
    static cudaStream_t st[3] = {nullptr, nullptr, nullptr};
    static cudaEvent_t evX = nullptr, evJ[3] = {nullptr, nullptr, nullptr};
    if (!st[0]) {
        for (int i = 0; i < 3; i++) {
            cudaStreamCreateWithFlags(&st[i], cudaStreamNonBlocking);
            cudaEventCreateWithFlags(&evJ[i], cudaEventDisableTiming);
        }
        cudaEventCreateWithFlags(&evX, cudaEventDisableTiming);
    }

    const long psiR0[4] = {0, 8L * 65536, 16L * 65536, 24L * 65536};
    const long psiR1j1 = 4L * 8 * 65536;
    const long psiR1j2 = 4L * 8 * 65536 + 8L * 16384;
    const long psiR2j1 = 4L * 8 * 65536 + 16L * 16384;
    const long phiOff[4] = {0, 65536, 81920, 86016};

    // filters + input spectrum on the capture (default) stream
    kgen_psi<<<56, 256>>>(psi);
    kgen_phi<<<4, 256>>>(phi);
    kgen_tw<<<1, 128>>>(tw);
    kfwd_rows_real<<<1024, 256>>>(x, Xf, tw);
    kfwd_cols256<<<256, 256, SMC>>>(Xf, tw);

    cudaEventRecord(evX, 0);

    // ---- stream 1: s0 channel + full j1=1 chain ----
    cudaStreamWaitEvent(st[0], evX, 0);
    kphi16<<<16, 256, 0, st[0]>>>(Xf, phi, S, tw, 0, 1);
    k_first_small<128, 7, 512><<<128, 512, SM128, st[0]>>>(Xf, psi + psiR0[1], phi + phiOff[1], B1, S, tw, 9);
    k_second<64, 6, 2, 256><<<1024, 256, SM64, st[0]>>>(B1, psi + psiR1j1, phi + phiOff[2], S, tw, 225);
    k_second<32, 5, 4, 128><<<1024, 128, SM32, st[0]>>>(B1, psi + psiR1j2, phi + phiOff[3], S, tw, 289);
    cudaEventRecord(evJ[0], st[0]);

    // ---- stream 2: j1=2 chain ----
    cudaStreamWaitEvent(st[1], evX, 0);
    k_first_small<64, 6, 256><<<128, 256, SM64, st[1]>>>(Xf, psi + psiR0[2], phi + phiOff[2], B2, S, tw, 17);
    k_second<32, 5, 2, 128><<<1024, 128, SM32, st[1]>>>(B2, psi + psiR2j1, phi + phiOff[3], S, tw, 353);
    cudaEventRecord(evJ[1], st[1]);

    // ---- stream 3: j1=3 chain ----
    cudaStreamWaitEvent(st[2], evX, 0);
    k_first_small<32, 5, 128><<<128, 128, SM32, st[2]>>>(Xf, psi + psiR0[3], phi + phiOff[3], B3, S, tw, 25);
    cudaEventRecord(evJ[2], st[2]);

    // ---- default stream: j1=0 full-res chain + its second order ----
    kfilt_rows<<<8192, 256>>>(Xf, psi, A, tw);
    kcols_mod256<<<2048, 256, SMC>>>(A, B, tw);
    kfwd_rows<<<8192, 256>>>(B, tw);
    kphi16<<<128, 256>>>(B, phi, S, tw, 1, 8);
    k_second<128, 7, 2, 512><<<1024, 512, SM128>>>(B, psi + psiR0[1], phi + phiOff[1], S, tw, 33);
    k_second< 64, 6, 4, 256><<<1024, 256, SM64 >>>(B, psi + psiR0[2], phi + phiOff[2], S, tw, 97);
    k_second< 32, 5, 8, 128><<<1024, 128, SM32 >>>(B, psi + psiR0[3], phi + phiOff[3], S, tw, 161);

    // join
    cudaStreamWaitEvent(0, evJ[0], 0);
    cudaStreamWaitEvent(0, evJ[1], 0);
    cudaStreamWaitEvent(0, evJ[2], 0);

    // MLP
    dim3 g1(2, 128);
    kgemm1<<<g1, 256>>>(S, w1, part);
    kred1<<<64, 256>>>(part, b1, bn1g, bn1b, bn1m, bn1v, h1);
    kfc_bn<<<(16 * 512 + 255) / 256, 256>>>(h1, w2, b2, bn2g, bn2b, bn2m, bn2v, h2, 1024, 512);
    kfc_bn<<<(16 * 128 + 255) / 256, 256>>>(h2, w3, b3, bn3g, bn3b, bn3m, bn3v, h3, 512, 128);
    kfc4<<<16, 128>>>(h3, w4, b4, (float*)d_out);
}